// round 2
// baseline (speedup 1.0000x reference)
#include <cuda_runtime.h>
#include <cstdint>
#include <math.h>

// Shapes (fixed by the problem)
//  B=64, D=4096, H=32, HKV=8, DH=128, W=2048, G=4

typedef unsigned long long u64;

// ------------------------------------------------------------------
// Scratch (device globals; no allocation allowed)
// ------------------------------------------------------------------
__device__ float g_qkv_part[8 * 64 * 6144];   // split-K partials for fused QKV
__device__ float g_q[64 * 4096];              // q after RoPE
__device__ float g_knew[64 * 1024];           // k_new after RoPE
__device__ float g_vnew[64 * 1024];
__device__ float g_attn[64 * 4096];           // attention output (pre W_o)
__device__ float g_opart[8 * 64 * 4096];      // split-K partials for O proj
__device__ float g_obuf[64 * 4096];           // out = attn @ W_o^T
__device__ float g_gpart[16 * 64 * 4096];     // split-K partials for gate

// ------------------------------------------------------------------
// packed f32x2 helpers (FFMA2 path — PTX only, sm_100+)
// ------------------------------------------------------------------
__device__ __forceinline__ u64 pk2(float x, float y) {
    u64 r; asm("mov.b64 %0, {%1, %2};" : "=l"(r) : "f"(x), "f"(y)); return r;
}
__device__ __forceinline__ void upk2(u64 v, float& x, float& y) {
    asm("mov.b64 {%0, %1}, %2;" : "=f"(x), "=f"(y) : "l"(v));
}
__device__ __forceinline__ u64 ffma2(u64 a, u64 b, u64 c) {
    u64 d; asm("fma.rn.f32x2 %0, %1, %2, %3;" : "=l"(d) : "l"(a), "l"(b), "l"(c)); return d;
}

// ------------------------------------------------------------------
// GEMM: C[64, N] = A[64, Ktot] @ B[N, Ktot]^T, split-K partials.
// mode 0: A = x,           B = Wq|Wk|Wv regions, C = g_qkv_part, N=6144
// mode 1: A = g_attn,      B = Wo,               C = g_opart,    N=4096
// mode 2: A = x ‖ g_obuf,  B = gate_w,           C = g_gpart,    N=4096
// Block: 256 thr, 64x64 tile, 16-deep k stages, double-buffered smem.
// Per thread: 4x4 outputs packed as f32x2 pairs along m.
// ------------------------------------------------------------------
__global__ __launch_bounds__(256) void gemm64(
    int mode,
    const float* __restrict__ xp,
    const float* __restrict__ B0, const float* __restrict__ B1, const float* __restrict__ B2,
    int Ktot, int N, int Kc)
{
    __shared__ float As[2][16][68];
    __shared__ float Bs[2][16][68];

    const float* A0 = (mode == 1) ? g_attn : xp;
    const float* A1 = (mode == 2) ? g_obuf : nullptr;
    float* Cp = (mode == 0) ? g_qkv_part : (mode == 1) ? g_opart : g_gpart;

    const int tid = threadIdx.x;
    const int n0  = blockIdx.x * 64;
    const int sp  = blockIdx.y;
    const int kb  = sp * Kc;

    // loader mapping: 64 rows x 16 k, one float4 per thread
    const int lr = tid >> 2;         // 0..63
    const int lk = (tid & 3) << 2;   // 0,4,8,12

    const float* Brow;
    {
        int ng = n0 + lr;
        if (B1 != nullptr && ng >= 4096)
            Brow = (ng < 5120) ? (B1 + (size_t)(ng - 4096) * Ktot)
                               : (B2 + (size_t)(ng - 5120) * Ktot);
        else
            Brow = B0 + (size_t)ng * Ktot;
    }

    // compute mapping: 16x16 thread grid of 4x4 micro-tiles
    const int tmq = tid >> 4;          // 0..15 -> m0 = tmq*4
    const int tn  = (tid & 15) << 2;   // 0..60

    u64 c0[4], c1[4];
#pragma unroll
    for (int i = 0; i < 4; i++) { c0[i] = 0ull; c1[i] = 0ull; }

    const int T = Kc / 16;
    float4 av, bv;

    // prologue: load stage 0
    {
        int kk = kb + lk;
        if (A1 == nullptr) av = *(const float4*)(A0 + (size_t)lr * Ktot + kk);
        else av = (kk < 4096) ? *(const float4*)(A0 + (size_t)lr * 4096 + kk)
                              : *(const float4*)(A1 + (size_t)lr * 4096 + (kk - 4096));
        bv = *(const float4*)(Brow + kk);
        As[0][lk + 0][lr] = av.x; As[0][lk + 1][lr] = av.y;
        As[0][lk + 2][lr] = av.z; As[0][lk + 3][lr] = av.w;
        Bs[0][lk + 0][lr] = bv.x; Bs[0][lk + 1][lr] = bv.y;
        Bs[0][lk + 2][lr] = bv.z; Bs[0][lk + 3][lr] = bv.w;
    }
    __syncthreads();

    for (int t = 0; t < T; t++) {
        const int cur = t & 1;
        if (t + 1 < T) {
            int kk = kb + (t + 1) * 16 + lk;
            if (A1 == nullptr) av = *(const float4*)(A0 + (size_t)lr * Ktot + kk);
            else av = (kk < 4096) ? *(const float4*)(A0 + (size_t)lr * 4096 + kk)
                                  : *(const float4*)(A1 + (size_t)lr * 4096 + (kk - 4096));
            bv = *(const float4*)(Brow + kk);
        }
#pragma unroll
        for (int k = 0; k < 16; k++) {
            float4 a4 = *(const float4*)&As[cur][k][tmq << 2];
            float4 b4 = *(const float4*)&Bs[cur][k][tn];
            u64 a01 = pk2(a4.x, a4.y);
            u64 a23 = pk2(a4.z, a4.w);
            u64 bb;
            bb = pk2(b4.x, b4.x); c0[0] = ffma2(a01, bb, c0[0]); c1[0] = ffma2(a23, bb, c1[0]);
            bb = pk2(b4.y, b4.y); c0[1] = ffma2(a01, bb, c0[1]); c1[1] = ffma2(a23, bb, c1[1]);
            bb = pk2(b4.z, b4.z); c0[2] = ffma2(a01, bb, c0[2]); c1[2] = ffma2(a23, bb, c1[2]);
            bb = pk2(b4.w, b4.w); c0[3] = ffma2(a01, bb, c0[3]); c1[3] = ffma2(a23, bb, c1[3]);
        }
        if (t + 1 < T) {
            const int nb = cur ^ 1;
            As[nb][lk + 0][lr] = av.x; As[nb][lk + 1][lr] = av.y;
            As[nb][lk + 2][lr] = av.z; As[nb][lk + 3][lr] = av.w;
            Bs[nb][lk + 0][lr] = bv.x; Bs[nb][lk + 1][lr] = bv.y;
            Bs[nb][lk + 2][lr] = bv.z; Bs[nb][lk + 3][lr] = bv.w;
            __syncthreads();
        }
    }

    // epilogue: unpack rows m0..m0+3, write float4 along n
    {
        const int m0 = tmq << 2;
        float r0[4], r1[4], r2[4], r3[4];
#pragma unroll
        for (int n = 0; n < 4; n++) {
            upk2(c0[n], r0[n], r1[n]);
            upk2(c1[n], r2[n], r3[n]);
        }
        float* base = Cp + ((size_t)sp * 64 + m0) * N + n0 + tn;
        *(float4*)(base + 0 * (size_t)N) = make_float4(r0[0], r0[1], r0[2], r0[3]);
        *(float4*)(base + 1 * (size_t)N) = make_float4(r1[0], r1[1], r1[2], r1[3]);
        *(float4*)(base + 2 * (size_t)N) = make_float4(r2[0], r2[1], r2[2], r2[3]);
        *(float4*)(base + 3 * (size_t)N) = make_float4(r3[0], r3[1], r3[2], r3[3]);
    }
}

// ------------------------------------------------------------------
// Reduce QKV split-K partials + apply RoPE to q and k_new.
// One thread per (row, col-pair). Total pairs = 64*6144/2 = 196608.
// qkv column layout: [0,4096) = q, [4096,5120) = k_new, [5120,6144) = v_new.
// ------------------------------------------------------------------
__global__ __launch_bounds__(256) void reduce_qkv_rope(const int* __restrict__ posp)
{
    int idx = blockIdx.x * 256 + threadIdx.x;    // pair index
    int b = idx / 3072;
    int col = (idx - b * 3072) * 2;

    const float* p = g_qkv_part + (size_t)b * 6144 + col;
    float s0 = 0.f, s1 = 0.f;
#pragma unroll
    for (int s = 0; s < 8; s++) {
        s0 += p[(size_t)s * 64 * 6144];
        s1 += p[(size_t)s * 64 * 6144 + 1];
    }

    int praw = *posp;
    int pos = praw;
    if (pos < 0 || pos > (1 << 26)) {            // defensive: pos passed as float bits
        float pf = __int_as_float(praw);
        pos = (int)pf;
    }

    if (col < 5120) {
        int d = col & 127;                        // even pair offset within a 128-head
        double inv = pow(10000.0, -(double)d * (1.0 / 128.0));
        double ang = (double)pos * inv;
        double sn, cn;
        sincos(ang, &sn, &cn);
        float c = (float)cn, s = (float)sn;
        float o0 = s0 * c - s1 * s;
        float o1 = s0 * s + s1 * c;
        if (col < 4096) {
            g_q[(size_t)b * 4096 + col]     = o0;
            g_q[(size_t)b * 4096 + col + 1] = o1;
        } else {
            g_knew[(size_t)b * 1024 + (col - 4096)]     = o0;
            g_knew[(size_t)b * 1024 + (col - 4096) + 1] = o1;
        }
    } else {
        g_vnew[(size_t)b * 1024 + (col - 5120)]     = s0;
        g_vnew[(size_t)b * 1024 + (col - 5120) + 1] = s1;
    }
}

// ------------------------------------------------------------------
// Attention: one block per (b, kv-head). 8 warps, warp-per-key.
// Sliding window: effective key w -> cache slot w+1 for w<2047, k_new at 2047.
// ------------------------------------------------------------------
__global__ __launch_bounds__(256) void attn_kernel(
    const float* __restrict__ kc, const float* __restrict__ vc)
{
    __shared__ float sc[4 * 2048];   // scores; later aliased as out partials [8][4][128]
    __shared__ float red[8];
    __shared__ float s_mx[4];
    __shared__ float s_inv[4];

    const int b  = blockIdx.x;
    const int kh = blockIdx.y;
    const int warp = threadIdx.x >> 5;
    const int lane = threadIdx.x & 31;

    // 4 query heads of this kv group, each lane owns elems lane*4..+3
    const float* qp = g_q + (size_t)b * 4096 + kh * 512;
    float4 q0 = *(const float4*)(qp + 0 * 128 + lane * 4);
    float4 q1 = *(const float4*)(qp + 1 * 128 + lane * 4);
    float4 q2 = *(const float4*)(qp + 2 * 128 + lane * 4);
    float4 q3 = *(const float4*)(qp + 3 * 128 + lane * 4);

    const size_t bh = (size_t)(b * 8 + kh);
    const float* kbase = kc + bh * (2048 * 128);
    const float* vbase = vc + bh * (2048 * 128);
    const float* knew  = g_knew + bh * 128;
    const float* vnew  = g_vnew + bh * 128;
    const float scale = 0.08838834764831845f;   // 1/sqrt(128)

    const int base = warp * 256;                // 256 contiguous keys per warp

    // ---------------- score phase ----------------
    {
        float4 kr[2][8];
#pragma unroll
        for (int u = 0; u < 8; u++) {
            int w = base + u;
            const float* p = (w < 2047) ? (kbase + (size_t)(w + 1) * 128) : knew;
            kr[0][u] = *(const float4*)(p + lane * 4);
        }
        for (int j0 = 0; j0 < 256; j0 += 8) {
            int cur = (j0 >> 3) & 1;
            if (j0 + 8 < 256) {
#pragma unroll
                for (int u = 0; u < 8; u++) {
                    int w = base + j0 + 8 + u;
                    const float* p = (w < 2047) ? (kbase + (size_t)(w + 1) * 128) : knew;
                    kr[cur ^ 1][u] = *(const float4*)(p + lane * 4);
                }
            }
#pragma unroll
            for (int u = 0; u < 8; u++) {
                int w = base + j0 + u;
                float4 k4 = kr[cur][u];
                float p0 = q0.x * k4.x + q0.y * k4.y + q0.z * k4.z + q0.w * k4.w;
                float p1 = q1.x * k4.x + q1.y * k4.y + q1.z * k4.z + q1.w * k4.w;
                float p2 = q2.x * k4.x + q2.y * k4.y + q2.z * k4.z + q2.w * k4.w;
                float p3 = q3.x * k4.x + q3.y * k4.y + q3.z * k4.z + q3.w * k4.w;
#pragma unroll
                for (int off = 16; off > 0; off >>= 1) {
                    p0 += __shfl_xor_sync(0xffffffffu, p0, off);
                    p1 += __shfl_xor_sync(0xffffffffu, p1, off);
                    p2 += __shfl_xor_sync(0xffffffffu, p2, off);
                    p3 += __shfl_xor_sync(0xffffffffu, p3, off);
                }
                if (lane < 4) {
                    float pv = (lane == 0) ? p0 : (lane == 1) ? p1 : (lane == 2) ? p2 : p3;
                    sc[lane * 2048 + w] = pv * scale;
                }
            }
        }
    }
    __syncthreads();

    // ---------------- softmax (unnormalized exp; 1/sum applied at the end) ----
    for (int g = 0; g < 4; g++) {
        float* row = sc + g * 2048;
        float mx = -3.0e38f;
        for (int w = threadIdx.x; w < 2048; w += 256) mx = fmaxf(mx, row[w]);
#pragma unroll
        for (int off = 16; off > 0; off >>= 1)
            mx = fmaxf(mx, __shfl_xor_sync(0xffffffffu, mx, off));
        if (lane == 0) red[warp] = mx;
        __syncthreads();
        if (threadIdx.x == 0) {
            float m = red[0];
            for (int i = 1; i < 8; i++) m = fmaxf(m, red[i]);
            s_mx[g] = m;
        }
        __syncthreads();
        mx = s_mx[g];
        float sum = 0.f;
        for (int w = threadIdx.x; w < 2048; w += 256) {
            float e = expf(row[w] - mx);
            row[w] = e;
            sum += e;
        }
#pragma unroll
        for (int off = 16; off > 0; off >>= 1)
            sum += __shfl_xor_sync(0xffffffffu, sum, off);
        if (lane == 0) red[warp] = sum;
        __syncthreads();
        if (threadIdx.x == 0) {
            float s = 0.f;
            for (int i = 0; i < 8; i++) s += red[i];
            s_inv[g] = 1.0f / s;
        }
        __syncthreads();
    }

    // ---------------- p @ V phase ----------------
    float4 a0 = make_float4(0, 0, 0, 0), a1 = a0, a2 = a0, a3 = a0;
    {
        float4 vr[2][8];
#pragma unroll
        for (int u = 0; u < 8; u++) {
            int w = base + u;
            const float* p = (w < 2047) ? (vbase + (size_t)(w + 1) * 128) : vnew;
            vr[0][u] = *(const float4*)(p + lane * 4);
        }
        for (int j0 = 0; j0 < 256; j0 += 8) {
            int cur = (j0 >> 3) & 1;
            if (j0 + 8 < 256) {
#pragma unroll
                for (int u = 0; u < 8; u++) {
                    int w = base + j0 + 8 + u;
                    const float* p = (w < 2047) ? (vbase + (size_t)(w + 1) * 128) : vnew;
                    vr[cur ^ 1][u] = *(const float4*)(p + lane * 4);
                }
            }
#pragma unroll
            for (int u = 0; u < 8; u++) {
                int w = base + j0 + u;
                float4 v4 = vr[cur][u];
                float p0 = sc[w];
                float p1 = sc[2048 + w];
                float p2 = sc[4096 + w];
                float p3 = sc[6144 + w];
                a0.x += p0 * v4.x; a0.y += p0 * v4.y; a0.z += p0 * v4.z; a0.w += p0 * v4.w;
                a1.x += p1 * v4.x; a1.y += p1 * v4.y; a1.z += p1 * v4.z; a1.w += p1 * v4.w;
                a2.x += p2 * v4.x; a2.y += p2 * v4.y; a2.z += p2 * v4.z; a2.w += p2 * v4.w;
                a3.x += p3 * v4.x; a3.y += p3 * v4.y; a3.z += p3 * v4.z; a3.w += p3 * v4.w;
            }
        }
    }
    __syncthreads();   // all warps done reading sc -> safe to alias

    // cross-warp reduction through smem (alias of sc)
    float* outp = sc;  // [8 warps][4 g][128 d] = 4096 floats
    *(float4*)&outp[warp * 512 + 0 * 128 + lane * 4] = a0;
    *(float4*)&outp[warp * 512 + 1 * 128 + lane * 4] = a1;
    *(float4*)&outp[warp * 512 + 2 * 128 + lane * 4] = a2;
    *(float4*)&outp[warp * 512 + 3 * 128 + lane * 4] = a3;
    __syncthreads();

    for (int oi = threadIdx.x; oi < 512; oi += 256) {
        int g = oi >> 7;
        float s = 0.f;
#pragma unroll
        for (int w8 = 0; w8 < 8; w8++) s += outp[w8 * 512 + oi];
        g_attn[(size_t)b * 4096 + kh * 512 + oi] = s * s_inv[g];
    }
}

// ------------------------------------------------------------------
// Reduce O split-K partials
// ------------------------------------------------------------------
__global__ __launch_bounds__(256) void reduce_o()
{
    int idx = blockIdx.x * 256 + threadIdx.x;   // < 262144
    float s = 0.f;
#pragma unroll
    for (int sp = 0; sp < 8; sp++) s += g_opart[(size_t)sp * 262144 + idx];
    g_obuf[idx] = s;
}

// ------------------------------------------------------------------
// Reduce gate partials + bias + sigmoid + residual
// ------------------------------------------------------------------
__global__ __launch_bounds__(256) void reduce_gate(
    const float* __restrict__ gb, const float* __restrict__ x, float* __restrict__ out)
{
    int idx = blockIdx.x * 256 + threadIdx.x;   // < 262144
    int i = idx & 4095;
    float s = gb[i];
#pragma unroll
    for (int sp = 0; sp < 16; sp++) s += g_gpart[(size_t)sp * 262144 + idx];
    float g = 1.0f / (1.0f + expf(-s));
    out[idx] = x[idx] + g * g_obuf[idx];
}

// ------------------------------------------------------------------
// Launch
// ------------------------------------------------------------------
extern "C" void kernel_launch(void* const* d_in, const int* in_sizes, int n_in,
                              void* d_out, int out_size)
{
    const float* x  = (const float*)d_in[0];
    const float* kc = (const float*)d_in[1];
    const float* vc = (const float*)d_in[2];
    const float* Wq = (const float*)d_in[3];
    const float* Wk = (const float*)d_in[4];
    const float* Wv = (const float*)d_in[5];
    const float* Wo = (const float*)d_in[6];
    const float* gw = (const float*)d_in[7];
    const float* gb = (const float*)d_in[8];
    const int*   pp = (const int*)d_in[9];
    float* out = (float*)d_out;

    // Fused QKV projection: [64,4096] @ [6144,4096]^T, split-K 8
    gemm64<<<dim3(96, 8), 256>>>(0, x, Wq, Wk, Wv, 4096, 6144, 512);
    reduce_qkv_rope<<<768, 256>>>(pp);

    // Sliding-window GQA attention
    attn_kernel<<<dim3(64, 8), 256>>>(kc, vc);

    // O projection: [64,4096] @ [4096,4096]^T, split-K 8
    gemm64<<<dim3(64, 8), 256>>>(1, x, Wo, nullptr, nullptr, 4096, 4096, 512);
    reduce_o<<<1024, 256>>>();

    // Gate: [64, 8192 (x ‖ out)] @ [4096,8192]^T, split-K 16
    gemm64<<<dim3(64, 16), 256>>>(2, x, gw, nullptr, nullptr, 8192, 4096, 512);
    reduce_gate<<<1024, 256>>>(gb, x, out);
}

// round 5
// speedup vs baseline: 1.4138x; 1.4138x over previous
#include <cuda_runtime.h>
#include <cstdint>
#include <math.h>

// Shapes: B=64, D=4096, H=32, HKV=8, DH=128, W=2048, G=4
typedef unsigned long long u64;

// ------------------------------------------------------------------
// Scratch (device globals; no allocation allowed)
// ------------------------------------------------------------------
__device__ float g_qkv_part[16 * 64 * 6144];  // split-K partials, fused QKV
__device__ float g_q[64 * 4096];              // q after RoPE (scaled by 1/sqrt(DH))
__device__ float g_knew[64 * 1024];           // k_new after RoPE
__device__ float g_vnew[64 * 1024];
__device__ float g_attn[64 * 4096];           // attention output (pre W_o)
__device__ float g_opart[16 * 64 * 4096];     // split-K partials, O proj
__device__ float g_obuf[64 * 4096];           // out = attn @ W_o^T
__device__ float g_gpart[32 * 64 * 4096];     // split-K partials, gate
__device__ float g_rc[64];                    // RoPE cos table (fp64-exact)
__device__ float g_rs[64];                    // RoPE sin table

// ------------------------------------------------------------------
// packed f32x2 helpers
// ------------------------------------------------------------------
__device__ __forceinline__ u64 pk2(float x, float y) {
    u64 r; asm("mov.b64 %0, {%1, %2};" : "=l"(r) : "f"(x), "f"(y)); return r;
}
__device__ __forceinline__ void upk2(u64 v, float& x, float& y) {
    asm("mov.b64 {%0, %1}, %2;" : "=f"(x), "=f"(y) : "l"(v));
}
__device__ __forceinline__ u64 ffma2(u64 a, u64 b, u64 c) {
    u64 d; asm("fma.rn.f32x2 %0, %1, %2, %3;" : "=l"(d) : "l"(a), "l"(b), "l"(c)); return d;
}

// ------------------------------------------------------------------
// GEMM v2: C[64, N] = A[64, Ktot] @ B[N, Ktot]^T, split-K partials.
// Block tile 64m x 256n, 256 threads, per-thread 8m x 8n (n split as
// nA = (tid&31)*4 and nB = nA+128 for conflict-free LDS.128).
// ------------------------------------------------------------------
__global__ __launch_bounds__(256, 2) void gemm_v2(
    int mode, const float* __restrict__ x,
    const float* __restrict__ B0, const float* __restrict__ B1, const float* __restrict__ B2,
    int KtotB, int N, int Kc)
{
    __shared__ float As[2][16][68];
    __shared__ float Bs[2][16][260];

    const int tid = threadIdx.x;
    const int n0  = blockIdx.x * 256;
    const int sp  = blockIdx.y;
    const int kb  = sp * Kc;

    // ---- A source (all A matrices are 64 x 4096 row-major) ----
    const float* Abase;
    int koff = kb;
    if (mode == 0) Abase = x;
    else if (mode == 1) Abase = g_attn;
    else { if (kb < 4096) Abase = x; else { Abase = g_obuf; koff = kb - 4096; } }

    // ---- B region (block-uniform: 4096/5120 boundaries are 256-aligned) ----
    const float* Bb = B0;
    int nr = n0;
    if (mode == 0 && n0 >= 4096) {
        if (n0 < 5120) { Bb = B1; nr = n0 - 4096; }
        else           { Bb = B2; nr = n0 - 5120; }
    }

    float* Cp = (mode == 0) ? g_qkv_part : (mode == 1) ? g_opart : g_gpart;

    // ---- loader mapping: 64 rows x 16 k, one float4 per thread per matrix ----
    const int lr  = tid >> 2;        // 0..63
    const int lk4 = (tid & 3) << 2;  // 0,4,8,12
    const float* arow  = Abase + (size_t)lr * 4096 + koff + lk4;
    const float* brow0 = Bb + (size_t)(nr + lr +   0) * KtotB + kb + lk4;
    const float* brow1 = Bb + (size_t)(nr + lr +  64) * KtotB + kb + lk4;
    const float* brow2 = Bb + (size_t)(nr + lr + 128) * KtotB + kb + lk4;
    const float* brow3 = Bb + (size_t)(nr + lr + 192) * KtotB + kb + lk4;

    // ---- compute mapping ----
    const int m0 = (tid >> 5) << 3;      // 0,8,..,56 (warp-uniform)
    const int nA = (tid & 31) << 2;      // 0..124
    const int nB = nA + 128;

    u64 cA[8][2], cB[8][2];
#pragma unroll
    for (int m = 0; m < 8; m++) { cA[m][0]=0; cA[m][1]=0; cB[m][0]=0; cB[m][1]=0; }

    const int T = Kc >> 4;
    float4 av, bv0, bv1, bv2, bv3;

    // prologue: load + store stage 0
    av  = *(const float4*)(arow);
    bv0 = *(const float4*)(brow0);
    bv1 = *(const float4*)(brow1);
    bv2 = *(const float4*)(brow2);
    bv3 = *(const float4*)(brow3);
    As[0][lk4+0][lr]=av.x; As[0][lk4+1][lr]=av.y; As[0][lk4+2][lr]=av.z; As[0][lk4+3][lr]=av.w;
    Bs[0][lk4+0][lr    ]=bv0.x; Bs[0][lk4+1][lr    ]=bv0.y; Bs[0][lk4+2][lr    ]=bv0.z; Bs[0][lk4+3][lr    ]=bv0.w;
    Bs[0][lk4+0][lr+ 64]=bv1.x; Bs[0][lk4+1][lr+ 64]=bv1.y; Bs[0][lk4+2][lr+ 64]=bv1.z; Bs[0][lk4+3][lr+ 64]=bv1.w;
    Bs[0][lk4+0][lr+128]=bv2.x; Bs[0][lk4+1][lr+128]=bv2.y; Bs[0][lk4+2][lr+128]=bv2.z; Bs[0][lk4+3][lr+128]=bv2.w;
    Bs[0][lk4+0][lr+192]=bv3.x; Bs[0][lk4+1][lr+192]=bv3.y; Bs[0][lk4+2][lr+192]=bv3.z; Bs[0][lk4+3][lr+192]=bv3.w;
    __syncthreads();

    for (int t = 0; t < T; t++) {
        const int cur = t & 1;
        if (t + 1 < T) {
            const int ko = (t + 1) << 4;
            av  = *(const float4*)(arow  + ko);
            bv0 = *(const float4*)(brow0 + ko);
            bv1 = *(const float4*)(brow1 + ko);
            bv2 = *(const float4*)(brow2 + ko);
            bv3 = *(const float4*)(brow3 + ko);
        }
#pragma unroll
        for (int k = 0; k < 16; k++) {
            ulonglong2 bA  = *(const ulonglong2*)&Bs[cur][k][nA];
            ulonglong2 bBv = *(const ulonglong2*)&Bs[cur][k][nB];
            float4 a0 = *(const float4*)&As[cur][k][m0];
            float4 a1 = *(const float4*)&As[cur][k][m0 + 4];
            u64 s;
            s = pk2(a0.x, a0.x);
            cA[0][0]=ffma2(s,bA.x,cA[0][0]); cA[0][1]=ffma2(s,bA.y,cA[0][1]);
            cB[0][0]=ffma2(s,bBv.x,cB[0][0]); cB[0][1]=ffma2(s,bBv.y,cB[0][1]);
            s = pk2(a0.y, a0.y);
            cA[1][0]=ffma2(s,bA.x,cA[1][0]); cA[1][1]=ffma2(s,bA.y,cA[1][1]);
            cB[1][0]=ffma2(s,bBv.x,cB[1][0]); cB[1][1]=ffma2(s,bBv.y,cB[1][1]);
            s = pk2(a0.z, a0.z);
            cA[2][0]=ffma2(s,bA.x,cA[2][0]); cA[2][1]=ffma2(s,bA.y,cA[2][1]);
            cB[2][0]=ffma2(s,bBv.x,cB[2][0]); cB[2][1]=ffma2(s,bBv.y,cB[2][1]);
            s = pk2(a0.w, a0.w);
            cA[3][0]=ffma2(s,bA.x,cA[3][0]); cA[3][1]=ffma2(s,bA.y,cA[3][1]);
            cB[3][0]=ffma2(s,bBv.x,cB[3][0]); cB[3][1]=ffma2(s,bBv.y,cB[3][1]);
            s = pk2(a1.x, a1.x);
            cA[4][0]=ffma2(s,bA.x,cA[4][0]); cA[4][1]=ffma2(s,bA.y,cA[4][1]);
            cB[4][0]=ffma2(s,bBv.x,cB[4][0]); cB[4][1]=ffma2(s,bBv.y,cB[4][1]);
            s = pk2(a1.y, a1.y);
            cA[5][0]=ffma2(s,bA.x,cA[5][0]); cA[5][1]=ffma2(s,bA.y,cA[5][1]);
            cB[5][0]=ffma2(s,bBv.x,cB[5][0]); cB[5][1]=ffma2(s,bBv.y,cB[5][1]);
            s = pk2(a1.z, a1.z);
            cA[6][0]=ffma2(s,bA.x,cA[6][0]); cA[6][1]=ffma2(s,bA.y,cA[6][1]);
            cB[6][0]=ffma2(s,bBv.x,cB[6][0]); cB[6][1]=ffma2(s,bBv.y,cB[6][1]);
            s = pk2(a1.w, a1.w);
            cA[7][0]=ffma2(s,bA.x,cA[7][0]); cA[7][1]=ffma2(s,bA.y,cA[7][1]);
            cB[7][0]=ffma2(s,bBv.x,cB[7][0]); cB[7][1]=ffma2(s,bBv.y,cB[7][1]);
        }
        if (t + 1 < T) {
            const int nb = cur ^ 1;
            As[nb][lk4+0][lr]=av.x; As[nb][lk4+1][lr]=av.y; As[nb][lk4+2][lr]=av.z; As[nb][lk4+3][lr]=av.w;
            Bs[nb][lk4+0][lr    ]=bv0.x; Bs[nb][lk4+1][lr    ]=bv0.y; Bs[nb][lk4+2][lr    ]=bv0.z; Bs[nb][lk4+3][lr    ]=bv0.w;
            Bs[nb][lk4+0][lr+ 64]=bv1.x; Bs[nb][lk4+1][lr+ 64]=bv1.y; Bs[nb][lk4+2][lr+ 64]=bv1.z; Bs[nb][lk4+3][lr+ 64]=bv1.w;
            Bs[nb][lk4+0][lr+128]=bv2.x; Bs[nb][lk4+1][lr+128]=bv2.y; Bs[nb][lk4+2][lr+128]=bv2.z; Bs[nb][lk4+3][lr+128]=bv2.w;
            Bs[nb][lk4+0][lr+192]=bv3.x; Bs[nb][lk4+1][lr+192]=bv3.y; Bs[nb][lk4+2][lr+192]=bv3.z; Bs[nb][lk4+3][lr+192]=bv3.w;
            __syncthreads();
        }
    }

    // epilogue
    {
        float* base = Cp + ((size_t)sp * 64) * N + n0;
#pragma unroll
        for (int m = 0; m < 8; m++) {
            float f0, f1, f2, f3;
            upk2(cA[m][0], f0, f1); upk2(cA[m][1], f2, f3);
            *(float4*)(base + (size_t)(m0 + m) * N + nA) = make_float4(f0, f1, f2, f3);
            upk2(cB[m][0], f0, f1); upk2(cB[m][1], f2, f3);
            *(float4*)(base + (size_t)(m0 + m) * N + nB) = make_float4(f0, f1, f2, f3);
        }
    }
}

// ------------------------------------------------------------------
// RoPE table: 64 (cos,sin) pairs at fp64 accuracy, computed once.
// ------------------------------------------------------------------
__global__ void rope_tab(const int* __restrict__ posp)
{
    int i = threadIdx.x;   // 0..63
    int praw = *posp;
    int pos = praw;
    if (pos < 0 || pos > (1 << 26)) {   // defensive: pos passed as float bits
        float pf = __int_as_float(praw);
        pos = (int)pf;
    }
    double inv = pow(10000.0, -(double)(2 * i) / 128.0);
    double sn, cn;
    sincos((double)pos * inv, &sn, &cn);
    g_rc[i] = (float)cn;
    g_rs[i] = (float)sn;
}

// ------------------------------------------------------------------
// Reduce QKV split-K partials (16) + RoPE (table lookup, no fp64).
// q additionally scaled by 1/sqrt(DH).
// ------------------------------------------------------------------
__global__ __launch_bounds__(256) void reduce_qkv_rope()
{
    int idx = blockIdx.x * 256 + threadIdx.x;    // pair index, < 196608
    int b = idx / 3072;
    int col = (idx - b * 3072) * 2;

    const float* p = g_qkv_part + (size_t)b * 6144 + col;
    float s0 = 0.f, s1 = 0.f;
#pragma unroll
    for (int s = 0; s < 16; s++) {
        s0 += p[(size_t)s * 64 * 6144];
        s1 += p[(size_t)s * 64 * 6144 + 1];
    }

    const float qscale = 0.08838834764831845f;   // 1/sqrt(128)

    if (col < 5120) {
        int di = (col & 127) >> 1;               // pair index within head
        float c = g_rc[di], s = g_rs[di];
        float o0 = s0 * c - s1 * s;
        float o1 = s0 * s + s1 * c;
        if (col < 4096) {
            g_q[(size_t)b * 4096 + col]     = o0 * qscale;
            g_q[(size_t)b * 4096 + col + 1] = o1 * qscale;
        } else {
            g_knew[(size_t)b * 1024 + (col - 4096)]     = o0;
            g_knew[(size_t)b * 1024 + (col - 4096) + 1] = o1;
        }
    } else {
        g_vnew[(size_t)b * 1024 + (col - 5120)]     = s0;
        g_vnew[(size_t)b * 1024 + (col - 5120) + 1] = s1;
    }
}

// ------------------------------------------------------------------
// Attention: one block per (b, kv-head). 8 warps, warp-per-key.
// 6-shuffle multi-head reduction (no redux.f32 on sm_103a).
// Effective key w -> cache slot w+1 for w<2047, k_new/v_new at w=2047.
// ------------------------------------------------------------------
__global__ __launch_bounds__(256) void attn_kernel(
    const float* __restrict__ kc, const float* __restrict__ vc)
{
    __shared__ float sc[4 * 2048];   // scores; later aliased as out partials
    __shared__ float red[8];
    __shared__ float s_mx[4];
    __shared__ float s_inv[4];

    const int b    = blockIdx.x;
    const int kh   = blockIdx.y;
    const int warp = threadIdx.x >> 5;
    const int lane = threadIdx.x & 31;
    const unsigned FULL = 0xffffffffu;

    const float* qp = g_q + (size_t)b * 4096 + kh * 512;   // pre-scaled
    float4 q0 = *(const float4*)(qp + 0 * 128 + lane * 4);
    float4 q1 = *(const float4*)(qp + 1 * 128 + lane * 4);
    float4 q2 = *(const float4*)(qp + 2 * 128 + lane * 4);
    float4 q3 = *(const float4*)(qp + 3 * 128 + lane * 4);

    const size_t bh = (size_t)(b * 8 + kh);
    const float* kbase = kc + bh * (2048 * 128);
    const float* vbase = vc + bh * (2048 * 128);
    const float* knew  = g_knew + bh * 128;
    const float* vnew  = g_vnew + bh * 128;

    const int base = warp * 256;     // 256 contiguous keys per warp
    const bool lo16 = (lane < 16);
    const bool b8   = (lane & 8) != 0;

    // ---------------- score phase ----------------
    {
        float4 kr[2][8];
#pragma unroll
        for (int u = 0; u < 8; u++) {
            int w = base + u;
            const float* p = (w < 2047) ? (kbase + (size_t)(w + 1) * 128) : knew;
            kr[0][u] = *(const float4*)(p + lane * 4);
        }
        for (int j0 = 0; j0 < 256; j0 += 8) {
            int cur = (j0 >> 3) & 1;
            if (j0 + 8 < 256) {
#pragma unroll
                for (int u = 0; u < 8; u++) {
                    int w = base + j0 + 8 + u;
                    const float* p = (w < 2047) ? (kbase + (size_t)(w + 1) * 128) : knew;
                    kr[cur ^ 1][u] = *(const float4*)(p + lane * 4);
                }
            }
#pragma unroll
            for (int u = 0; u < 8; u++) {
                int w = base + j0 + u;
                float4 k4 = kr[cur][u];
                float p0 = q0.x * k4.x + q0.y * k4.y + q0.z * k4.z + q0.w * k4.w;
                float p1 = q1.x * k4.x + q1.y * k4.y + q1.z * k4.z + q1.w * k4.w;
                float p2 = q2.x * k4.x + q2.y * k4.y + q2.z * k4.z + q2.w * k4.w;
                float p3 = q3.x * k4.x + q3.y * k4.y + q3.z * k4.z + q3.w * k4.w;
                // 6-shuffle 4-head reduction:
                // A: fold halves; low half accumulates p0/p1, high p2/p3
                float xa = lo16 ? p2 : p0;
                float ya = __shfl_xor_sync(FULL, xa, 16);
                float pA = lo16 ? (p0 + ya) : (p2 + ya);
                float xb = lo16 ? p3 : p1;
                float yb = __shfl_xor_sync(FULL, xb, 16);
                float pB = lo16 ? (p1 + yb) : (p3 + yb);
                // B: specialize 8-lane groups (even group: pA-line, odd: pB-line)
                float xc = b8 ? pA : pB;
                float yc = __shfl_xor_sync(FULL, xc, 8);
                float pC = b8 ? (pB + yc) : (pA + yc);
                // C: butterfly within 8-lane group
                pC += __shfl_xor_sync(FULL, pC, 4);
                pC += __shfl_xor_sync(FULL, pC, 2);
                pC += __shfl_xor_sync(FULL, pC, 1);
                // lanes 0,8,16,24 hold heads 0,1,2,3
                if ((lane & 7) == 0) sc[(lane >> 3) * 2048 + w] = pC;
            }
        }
    }
    __syncthreads();

    // ---------------- softmax (unnormalized exp; 1/sum in epilogue) ----------
    for (int g = 0; g < 4; g++) {
        float* row = sc + g * 2048;
        float mx = -3.0e38f;
        for (int w = threadIdx.x; w < 2048; w += 256) mx = fmaxf(mx, row[w]);
#pragma unroll
        for (int off = 16; off > 0; off >>= 1)
            mx = fmaxf(mx, __shfl_xor_sync(FULL, mx, off));
        if (lane == 0) red[warp] = mx;
        __syncthreads();
        if (threadIdx.x == 0) {
            float m = red[0];
            for (int i = 1; i < 8; i++) m = fmaxf(m, red[i]);
            s_mx[g] = m;
        }
        __syncthreads();
        mx = s_mx[g];
        float sum = 0.f;
        for (int w = threadIdx.x; w < 2048; w += 256) {
            float e = expf(row[w] - mx);
            row[w] = e;
            sum += e;
        }
#pragma unroll
        for (int off = 16; off > 0; off >>= 1)
            sum += __shfl_xor_sync(FULL, sum, off);
        if (lane == 0) red[warp] = sum;
        __syncthreads();
        if (threadIdx.x == 0) {
            float s = 0.f;
            for (int i = 0; i < 8; i++) s += red[i];
            s_inv[g] = 1.0f / s;
        }
        __syncthreads();
    }

    // ---------------- p @ V phase ----------------
    float4 a0 = make_float4(0, 0, 0, 0), a1 = a0, a2 = a0, a3 = a0;
    {
        float4 vr[2][8];
#pragma unroll
        for (int u = 0; u < 8; u++) {
            int w = base + u;
            const float* p = (w < 2047) ? (vbase + (size_t)(w + 1) * 128) : vnew;
            vr[0][u] = *(const float4*)(p + lane * 4);
        }
        for (int j0 = 0; j0 < 256; j0 += 8) {
            int cur = (j0 >> 3) & 1;
            if (j0 + 8 < 256) {
#pragma unroll
                for (int u = 0; u < 8; u++) {
                    int w = base + j0 + 8 + u;
                    const float* p = (w < 2047) ? (vbase + (size_t)(w + 1) * 128) : vnew;
                    vr[cur ^ 1][u] = *(const float4*)(p + lane * 4);
                }
            }
#pragma unroll
            for (int u = 0; u < 8; u++) {
                int w = base + j0 + u;
                float4 v4 = vr[cur][u];
                float p0 = sc[w];
                float p1 = sc[2048 + w];
                float p2 = sc[4096 + w];
                float p3 = sc[6144 + w];
                a0.x += p0 * v4.x; a0.y += p0 * v4.y; a0.z += p0 * v4.z; a0.w += p0 * v4.w;
                a1.x += p1 * v4.x; a1.y += p1 * v4.y; a1.z += p1 * v4.z; a1.w += p1 * v4.w;
                a2.x += p2 * v4.x; a2.y += p2 * v4.y; a2.z += p2 * v4.z; a2.w += p2 * v4.w;
                a3.x += p3 * v4.x; a3.y += p3 * v4.y; a3.z += p3 * v4.z; a3.w += p3 * v4.w;
            }
        }
    }
    __syncthreads();   // all warps done reading sc -> safe to alias

    float* outp = sc;  // [8 warps][4 g][128 d]
    *(float4*)&outp[warp * 512 + 0 * 128 + lane * 4] = a0;
    *(float4*)&outp[warp * 512 + 1 * 128 + lane * 4] = a1;
    *(float4*)&outp[warp * 512 + 2 * 128 + lane * 4] = a2;
    *(float4*)&outp[warp * 512 + 3 * 128 + lane * 4] = a3;
    __syncthreads();

    for (int oi = threadIdx.x; oi < 512; oi += 256) {
        int g = oi >> 7;
        float s = 0.f;
#pragma unroll
        for (int w8 = 0; w8 < 8; w8++) s += outp[w8 * 512 + oi];
        g_attn[(size_t)b * 4096 + kh * 512 + oi] = s * s_inv[g];
    }
}

// ------------------------------------------------------------------
// Reduce O split-K partials (16)
// ------------------------------------------------------------------
__global__ __launch_bounds__(256) void reduce_o()
{
    int idx = blockIdx.x * 256 + threadIdx.x;   // < 262144
    float s = 0.f;
#pragma unroll
    for (int sp = 0; sp < 16; sp++) s += g_opart[(size_t)sp * 262144 + idx];
    g_obuf[idx] = s;
}

// ------------------------------------------------------------------
// Reduce gate partials (32) + bias + sigmoid + residual
// ------------------------------------------------------------------
__global__ __launch_bounds__(256) void reduce_gate(
    const float* __restrict__ gb, const float* __restrict__ x, float* __restrict__ out)
{
    int idx = blockIdx.x * 256 + threadIdx.x;   // < 262144
    int i = idx & 4095;
    float s = gb[i];
#pragma unroll
    for (int sp = 0; sp < 32; sp++) s += g_gpart[(size_t)sp * 262144 + idx];
    float g = 1.0f / (1.0f + expf(-s));
    out[idx] = x[idx] + g * g_obuf[idx];
}

// ------------------------------------------------------------------
// Launch
// ------------------------------------------------------------------
extern "C" void kernel_launch(void* const* d_in, const int* in_sizes, int n_in,
                              void* d_out, int out_size)
{
    const float* x  = (const float*)d_in[0];
    const float* kc = (const float*)d_in[1];
    const float* vc = (const float*)d_in[2];
    const float* Wq = (const float*)d_in[3];
    const float* Wk = (const float*)d_in[4];
    const float* Wv = (const float*)d_in[5];
    const float* Wo = (const float*)d_in[6];
    const float* gw = (const float*)d_in[7];
    const float* gb = (const float*)d_in[8];
    const int*   pp = (const int*)d_in[9];
    float* out = (float*)d_out;

    rope_tab<<<1, 64>>>(pp);

    // Fused QKV: [64,4096] @ [6144,4096]^T, n-tiles 24, split-K 16
    gemm_v2<<<dim3(24, 16), 256>>>(0, x, Wq, Wk, Wv, 4096, 6144, 256);
    reduce_qkv_rope<<<768, 256>>>();

    // Sliding-window GQA attention
    attn_kernel<<<dim3(64, 8), 256>>>(kc, vc);

    // O projection: n-tiles 16, split-K 16
    gemm_v2<<<dim3(16, 16), 256>>>(1, x, Wo, nullptr, nullptr, 4096, 4096, 256);
    reduce_o<<<1024, 256>>>();

    // Gate: [64, 8192 (x ‖ out)] @ [4096,8192]^T, n-tiles 16, split-K 32
    gemm_v2<<<dim3(16, 32), 256>>>(2, x, gw, nullptr, nullptr, 8192, 4096, 256);
    reduce_gate<<<1024, 256>>>(gb, x, out);
}